// round 1
// baseline (speedup 1.0000x reference)
#include <cuda_runtime.h>

// Problem constants
#define BB 256
#define TT 256
#define DD 512
#define HH 8
#define HD 64
#define MROWS (BB * TT)      // 65536
#define NQKV (3 * DD)        // 1536
#define KDIM DD              // 512

// Scratch (device globals; no allocation allowed)
__device__ float g_q[BB * HH * TT * HD];   // [B,H,T,HD]
__device__ float g_k[BB * HH * TT * HD];
__device__ float g_v[BB * HH * TT * HD];
__device__ float g_att[BB * TT * DD];      // [B,T,D]

// ---------------------------------------------------------------------------
// GEMM tile params: 128x128 block, BK=16, 256 threads, 8x8 per thread
// C[m,n] = sum_k A[m,k] * W[n,k]   (both row-major, K-contiguous)
// ---------------------------------------------------------------------------
#define BM 128
#define BN 128
#define BK 16

// Kernel 1: QKV projection + fused RoPE + scatter to [B,H,T,HD]
__global__ void __launch_bounds__(256) qkv_gemm_rope_kernel(
    const float* __restrict__ X,      // [M, K]
    const float* __restrict__ W,      // [1536, 512]
    const float* __restrict__ cosT,   // [T, HD]
    const float* __restrict__ sinT)   // [T, HD]
{
    __shared__ float As[BK][BM];
    __shared__ float Bs[BK][BN];

    const int bm = blockIdx.y * BM;
    const int bn = blockIdx.x * BN;
    const int tid = threadIdx.x;
    const int ty = tid >> 4;   // 0..15
    const int tx = tid & 15;   // 0..15

    float acc[8][8];
#pragma unroll
    for (int i = 0; i < 8; i++)
#pragma unroll
        for (int j = 0; j < 8; j++) acc[i][j] = 0.f;

    for (int kt = 0; kt < KDIM; kt += BK) {
#pragma unroll
        for (int l = 0; l < 2; l++) {
            int f = tid + l * 256;          // float4 index, 512 total
            int row = f >> 2;
            int kq = f & 3;
            float4 v = *(const float4*)(X + (size_t)(bm + row) * KDIM + kt + kq * 4);
            As[kq * 4 + 0][row] = v.x;
            As[kq * 4 + 1][row] = v.y;
            As[kq * 4 + 2][row] = v.z;
            As[kq * 4 + 3][row] = v.w;
        }
#pragma unroll
        for (int l = 0; l < 2; l++) {
            int f = tid + l * 256;
            int row = f >> 2;
            int kq = f & 3;
            float4 v = *(const float4*)(W + (size_t)(bn + row) * KDIM + kt + kq * 4);
            Bs[kq * 4 + 0][row] = v.x;
            Bs[kq * 4 + 1][row] = v.y;
            Bs[kq * 4 + 2][row] = v.z;
            Bs[kq * 4 + 3][row] = v.w;
        }
        __syncthreads();
#pragma unroll
        for (int kk = 0; kk < BK; kk++) {
            float a[8], b[8];
#pragma unroll
            for (int i = 0; i < 8; i++) a[i] = As[kk][ty * 8 + i];
#pragma unroll
            for (int j = 0; j < 8; j++) b[j] = Bs[kk][tx * 8 + j];
#pragma unroll
            for (int i = 0; i < 8; i++)
#pragma unroll
                for (int j = 0; j < 8; j++) acc[i][j] += a[i] * b[j];
        }
        __syncthreads();
    }

    // Epilogue: n -> (s, h, d); s is uniform per block (128-col tiles never
    // cross a 512 boundary). Apply RoPE for s<2, scatter to [B,H,T,HD].
    const int n0 = bn + tx * 8;
    const int s  = n0 >> 9;
    const int h  = (n0 >> 6) & 7;
    const int d0 = n0 & 63;         // even, pairs complete within the 8 cols
    float* dst = (s == 0) ? g_q : ((s == 1) ? g_k : g_v);

#pragma unroll
    for (int i = 0; i < 8; i++) {
        int m = bm + ty * 8 + i;
        int b = m >> 8;             // /T
        int t = m & 255;            // %T
        float vals[8];
#pragma unroll
        for (int j = 0; j < 8; j++) vals[j] = acc[i][j];
        if (s < 2) {
#pragma unroll
            for (int j = 0; j < 8; j += 2) {
                int d = d0 + j;
                float c  = cosT[t * HD + d];
                float sn = sinT[t * HD + d];
                float v0 = vals[j], v1 = vals[j + 1];
                vals[j]     = v0 * c - v1 * sn;
                vals[j + 1] = v1 * c + v0 * sn;
            }
        }
        size_t base = (((size_t)b * HH + h) * TT + t) * HD + d0;
#pragma unroll
        for (int j = 0; j < 8; j += 4) {
            float4 o = make_float4(vals[j], vals[j + 1], vals[j + 2], vals[j + 3]);
            *(float4*)(dst + base + j) = o;
        }
    }
}

// ---------------------------------------------------------------------------
// Kernel 2: causal flash attention. Block = one (b,h) x 64-row q tile.
// 256 threads (16x16); thread owns 4 rows x 4 cols.
// smem: Qs (plain), KP (K rotated per-row, then reused for P plain), Vs.
// ---------------------------------------------------------------------------
__global__ void __launch_bounds__(256) attn_kernel()
{
    const int qt = blockIdx.x;        // 0..3
    const int bh = blockIdx.y;        // 0..2047
    const float* Qg = g_q + ((size_t)bh * TT + qt * 64) * HD;
    const float* Kg = g_k + (size_t)bh * TT * HD;
    const float* Vg = g_v + (size_t)bh * TT * HD;

    __shared__ float Qs[64][64];
    __shared__ float KP[64][64];      // K (rotated), then P (plain)
    __shared__ float Vs[64][64];

    const int tid = threadIdx.x;
    const int ty = tid >> 4;
    const int tx = tid & 15;

    // Load Q tile (4096 floats = 1024 float4)
#pragma unroll
    for (int l = 0; l < 4; l++) {
        int f = tid + l * 256;
        int r = f >> 4, c4 = f & 15;
        *(float4*)&Qs[r][c4 * 4] = *(const float4*)(Qg + r * HD + c4 * 4);
    }

    float O[4][4];
    float mrow[4], lrow[4];
#pragma unroll
    for (int i = 0; i < 4; i++) {
        mrow[i] = -3.0e38f;
        lrow[i] = 0.f;
#pragma unroll
        for (int j = 0; j < 4; j++) O[i][j] = 0.f;
    }

    const float scale = 0.125f;   // 1/sqrt(64)

    for (int kt = 0; kt <= qt; kt++) {
        __syncthreads();   // previous PV reads (KP as P, Vs) finished
        // Load K tile (row-rotated to kill bank conflicts) and V tile
#pragma unroll
        for (int l = 0; l < 4; l++) {
            int f = tid + l * 256;
            int r = f >> 4, c4 = f & 15;
            const float* kp = Kg + ((size_t)kt * 64 + r) * HD + c4 * 4;
            float4 kv = *(const float4*)kp;
            int d0 = c4 * 4;
            KP[r][(d0 + 0 + r) & 63] = kv.x;
            KP[r][(d0 + 1 + r) & 63] = kv.y;
            KP[r][(d0 + 2 + r) & 63] = kv.z;
            KP[r][(d0 + 3 + r) & 63] = kv.w;
            *(float4*)&Vs[r][c4 * 4] =
                *(const float4*)(Vg + ((size_t)kt * 64 + r) * HD + c4 * 4);
        }
        __syncthreads();

        // S = Q @ K^T (K rows rotated: element (c,d) lives at KP[c][(d+c)&63])
        float S[4][4];
#pragma unroll
        for (int i = 0; i < 4; i++)
#pragma unroll
            for (int j = 0; j < 4; j++) S[i][j] = 0.f;

#pragma unroll 8
        for (int d = 0; d < 64; d++) {
            float a[4], b[4];
#pragma unroll
            for (int i = 0; i < 4; i++) a[i] = Qs[ty * 4 + i][d];
#pragma unroll
            for (int j = 0; j < 4; j++) {
                int c = tx * 4 + j;
                b[j] = KP[c][(d + c) & 63];
            }
#pragma unroll
            for (int i = 0; i < 4; i++)
#pragma unroll
                for (int j = 0; j < 4; j++) S[i][j] += a[i] * b[j];
        }

        // scale + causal mask (only diagonal tile needs masking)
        if (kt == qt) {
#pragma unroll
            for (int i = 0; i < 4; i++)
#pragma unroll
                for (int j = 0; j < 4; j++) {
                    int qr = ty * 4 + i, kc = tx * 4 + j;
                    S[i][j] = (kc > qr) ? -3.0e38f : S[i][j] * scale;
                }
        } else {
#pragma unroll
            for (int i = 0; i < 4; i++)
#pragma unroll
                for (int j = 0; j < 4; j++) S[i][j] *= scale;
        }

        // Online softmax per row (row replicated over 16 tx lanes)
#pragma unroll
        for (int i = 0; i < 4; i++) {
            float mloc = S[i][0];
#pragma unroll
            for (int j = 1; j < 4; j++) mloc = fmaxf(mloc, S[i][j]);
#pragma unroll
            for (int off = 8; off >= 1; off >>= 1)
                mloc = fmaxf(mloc, __shfl_xor_sync(0xffffffffu, mloc, off, 16));
            float mnew = fmaxf(mrow[i], mloc);
            float alpha = expf(mrow[i] - mnew);
            float psum = 0.f;
#pragma unroll
            for (int j = 0; j < 4; j++) {
                float p = expf(S[i][j] - mnew);
                S[i][j] = p;
                psum += p;
            }
#pragma unroll
            for (int off = 8; off >= 1; off >>= 1)
                psum += __shfl_xor_sync(0xffffffffu, psum, off, 16);
            lrow[i] = lrow[i] * alpha + psum;
            mrow[i] = mnew;
#pragma unroll
            for (int j = 0; j < 4; j++) O[i][j] *= alpha;
        }

        __syncthreads();   // all K reads done; safe to overwrite KP with P
#pragma unroll
        for (int i = 0; i < 4; i++) {
            float4 p4 = make_float4(S[i][0], S[i][1], S[i][2], S[i][3]);
            *(float4*)&KP[ty * 4 + i][tx * 4] = p4;
        }
        __syncthreads();

        // O += P @ V
#pragma unroll 8
        for (int c = 0; c < 64; c++) {
            float p[4], vv[4];
#pragma unroll
            for (int i = 0; i < 4; i++) p[i] = KP[ty * 4 + i][c];
#pragma unroll
            for (int j = 0; j < 4; j++) vv[j] = Vs[c][tx * 4 + j];
#pragma unroll
            for (int i = 0; i < 4; i++)
#pragma unroll
                for (int j = 0; j < 4; j++) O[i][j] += p[i] * vv[j];
        }
    }

    // Normalize and write to g_att[B,T,D]
    const int b = bh >> 3;
    const int h = bh & 7;
#pragma unroll
    for (int i = 0; i < 4; i++) {
        float inv = 1.f / lrow[i];
        int t = qt * 64 + ty * 4 + i;
        float4 o = make_float4(O[i][0] * inv, O[i][1] * inv,
                               O[i][2] * inv, O[i][3] * inv);
        *(float4*)(g_att + ((size_t)b * TT + t) * DD + h * HD + tx * 4) = o;
    }
}

// ---------------------------------------------------------------------------
// Kernel 3: output projection  out = g_att @ Wout^T
// ---------------------------------------------------------------------------
__global__ void __launch_bounds__(256) out_gemm_kernel(
    const float* __restrict__ W,     // [512, 512]
    float* __restrict__ out)         // [M, 512]
{
    __shared__ float As[BK][BM];
    __shared__ float Bs[BK][BN];

    const int bm = blockIdx.y * BM;
    const int bn = blockIdx.x * BN;
    const int tid = threadIdx.x;
    const int ty = tid >> 4;
    const int tx = tid & 15;

    float acc[8][8];
#pragma unroll
    for (int i = 0; i < 8; i++)
#pragma unroll
        for (int j = 0; j < 8; j++) acc[i][j] = 0.f;

    for (int kt = 0; kt < KDIM; kt += BK) {
#pragma unroll
        for (int l = 0; l < 2; l++) {
            int f = tid + l * 256;
            int row = f >> 2;
            int kq = f & 3;
            float4 v = *(const float4*)(g_att + (size_t)(bm + row) * KDIM + kt + kq * 4);
            As[kq * 4 + 0][row] = v.x;
            As[kq * 4 + 1][row] = v.y;
            As[kq * 4 + 2][row] = v.z;
            As[kq * 4 + 3][row] = v.w;
        }
#pragma unroll
        for (int l = 0; l < 2; l++) {
            int f = tid + l * 256;
            int row = f >> 2;
            int kq = f & 3;
            float4 v = *(const float4*)(W + (size_t)(bn + row) * KDIM + kt + kq * 4);
            Bs[kq * 4 + 0][row] = v.x;
            Bs[kq * 4 + 1][row] = v.y;
            Bs[kq * 4 + 2][row] = v.z;
            Bs[kq * 4 + 3][row] = v.w;
        }
        __syncthreads();
#pragma unroll
        for (int kk = 0; kk < BK; kk++) {
            float a[8], b[8];
#pragma unroll
            for (int i = 0; i < 8; i++) a[i] = As[kk][ty * 8 + i];
#pragma unroll
            for (int j = 0; j < 8; j++) b[j] = Bs[kk][tx * 8 + j];
#pragma unroll
            for (int i = 0; i < 8; i++)
#pragma unroll
                for (int j = 0; j < 8; j++) acc[i][j] += a[i] * b[j];
        }
        __syncthreads();
    }

#pragma unroll
    for (int i = 0; i < 8; i++) {
        size_t row = (size_t)(bm + ty * 8 + i);
#pragma unroll
        for (int j = 0; j < 8; j += 4) {
            float4 o = make_float4(acc[i][j], acc[i][j + 1],
                                   acc[i][j + 2], acc[i][j + 3]);
            *(float4*)(out + row * DD + bn + tx * 8 + j) = o;
        }
    }
}

// ---------------------------------------------------------------------------
extern "C" void kernel_launch(void* const* d_in, const int* in_sizes, int n_in,
                              void* d_out, int out_size)
{
    const float* x    = (const float*)d_in[0];   // [B,T,D]
    const float* cosT = (const float*)d_in[1];   // [T,HD]
    const float* sinT = (const float*)d_in[2];   // [T,HD]
    const float* Wqkv = (const float*)d_in[3];   // [1536,512]
    const float* Wout = (const float*)d_in[4];   // [512,512]
    float* out = (float*)d_out;                  // [B,T,D]

    dim3 g1(NQKV / BN, MROWS / BM);              // (12, 512)
    qkv_gemm_rope_kernel<<<g1, 256>>>(x, Wqkv, cosT, sinT);

    dim3 ga(TT / 64, BB * HH);                   // (4, 2048)
    attn_kernel<<<ga, 256>>>();

    dim3 g2(DD / BN, MROWS / BM);                // (4, 512)
    out_gemm_kernel<<<g2, 256>>>(Wout, out);
}

// round 5
// speedup vs baseline: 1.2699x; 1.2699x over previous
#include <cuda_runtime.h>
#include <cstdint>

// Problem constants
#define BB 256
#define TT 256
#define DD 512
#define HH 8
#define HD 64
#define KDIM 512

// Scratch (device globals; no allocation allowed)
__device__ float g_q[BB * HH * TT * HD];   // [B,H,T,HD]
__device__ float g_k[BB * HH * TT * HD];
__device__ float g_v[BB * HH * TT * HD];
__device__ float g_att[BB * TT * DD];      // [B,T,D]

// ---------------------------------------------------------------------------
// Portable (sm_80+) async-copy + mma.sync helpers
// ---------------------------------------------------------------------------
__device__ __forceinline__ uint32_t smem_u32(const void* p) {
    uint32_t a;
    asm("{ .reg .u64 t; cvta.to.shared.u64 t, %1; cvt.u32.u64 %0, t; }"
        : "=r"(a) : "l"(p));
    return a;
}

__device__ __forceinline__ void cp_async16(uint32_t dst, const void* src) {
    asm volatile("cp.async.cg.shared.global [%0], [%1], 16;"
                 :: "r"(dst), "l"(src) : "memory");
}
#define CP_COMMIT() asm volatile("cp.async.commit_group;" ::: "memory")
#define CP_WAIT1()  asm volatile("cp.async.wait_group 1;" ::: "memory")

__device__ __forceinline__ void mma_tf32(float* c, const uint32_t* a, const uint32_t* b) {
    asm volatile(
        "mma.sync.aligned.m16n8k8.row.col.f32.tf32.tf32.f32 "
        "{%0,%1,%2,%3}, {%4,%5,%6,%7}, {%8,%9}, {%0,%1,%2,%3};"
        : "+f"(c[0]), "+f"(c[1]), "+f"(c[2]), "+f"(c[3])
        : "r"(a[0]), "r"(a[1]), "r"(a[2]), "r"(a[3]), "r"(b[0]), "r"(b[1]));
}

__device__ __forceinline__ uint32_t tf32_rna(float x) {
    uint32_t u;
    asm("cvt.rna.tf32.f32 %0, %1;" : "=r"(u) : "f"(x));
    return u;
}

// split x into hi (tf32) + lo (tf32 of residual); hi+lo ~ fp32 accurate
__device__ __forceinline__ void split_tf32(float x, uint32_t& hi, uint32_t& lo) {
    hi = tf32_rna(x);
    lo = tf32_rna(x - __uint_as_float(hi));
}

// ---------------------------------------------------------------------------
// 3xTF32 tensor-core GEMM: C[128x128] = A[128xK] @ W[128xK]^T (both K-major)
// MODE 0: A = x; epilogue applies RoPE, scatters to g_q/g_k/g_v
// MODE 1: A = g_att; epilogue writes dst_out
// 256 threads = 8 warps (2 m x 4 n); warp tile 64x32; BK=32; 3-stage cp.async.
// smem row: 32 floats + 4 pad = 36 (fragment LDS conflict-free).
// Precision: per fragment split into tf32 hi+lo; C += Ah*Bh + Al*Bh + Ah*Bl.
// ---------------------------------------------------------------------------
#define STAGES 3
#define ROWF 36
#define STG_FLOATS (2 * 128 * ROWF)                 // A tile + B tile = 9216
#define SMEM_BYTES (STAGES * STG_FLOATS * 4)        // 110592

template <int MODE>
__global__ void __launch_bounds__(256) mma_gemm_kernel(
    const float* __restrict__ Ain,
    const float* __restrict__ W,
    const float* __restrict__ cosT,
    const float* __restrict__ sinT,
    float* __restrict__ dst_out)
{
    extern __shared__ float smem[];
    const uint32_t sb = smem_u32(smem);
    const float* A = (MODE == 0) ? Ain : (const float*)g_att;

    const int tid  = threadIdx.x;
    const int wid  = tid >> 5;
    const int lane = tid & 31;
    const int g    = lane >> 2;     // group 0..7
    const int q    = lane & 3;      // quad  0..3
    const int bm   = blockIdx.y * 128;
    const int bn   = blockIdx.x * 128;
    const int wm   = wid & 1;       // warp m index (2)
    const int wn   = wid >> 1;      // warp n index (4)

    float c[4][4][4];
#pragma unroll
    for (int mf = 0; mf < 4; mf++)
#pragma unroll
        for (int nf = 0; nf < 4; nf++)
#pragma unroll
            for (int r = 0; r < 4; r++) c[mf][nf][r] = 0.f;

    auto load_stage = [&](int s, int kt) {
        const uint32_t abase = sb + (uint32_t)s * STG_FLOATS * 4;
        const uint32_t bbase = abase + 128 * ROWF * 4;
        const float* ag = A + (size_t)bm * KDIM + kt * 32;
        const float* bg = W + (size_t)bn * KDIM + kt * 32;
#pragma unroll
        for (int i = 0; i < 4; i++) {
            int e   = tid + i * 256;
            int row = e >> 3;
            int k4  = e & 7;
            uint32_t so = (uint32_t)(row * ROWF + k4 * 4) * 4;
            cp_async16(abase + so, ag + (size_t)row * KDIM + k4 * 4);
            cp_async16(bbase + so, bg + (size_t)row * KDIM + k4 * 4);
        }
    };

    load_stage(0, 0); CP_COMMIT();
    load_stage(1, 1); CP_COMMIT();

#pragma unroll 1
    for (int kt = 0; kt < 16; kt++) {
        CP_WAIT1();
        __syncthreads();

        const float* As = smem + (kt % STAGES) * STG_FLOATS;
        const float* Bs = As + 128 * ROWF;
#pragma unroll
        for (int kk = 0; kk < 32; kk += 8) {
            uint32_t ah[4][4], al[4][4], bh[4][2], bl[4][2];
#pragma unroll
            for (int mf = 0; mf < 4; mf++) {
                int r0 = wm * 64 + mf * 16 + g;
                split_tf32(As[r0 * ROWF + kk + q],           ah[mf][0], al[mf][0]);
                split_tf32(As[(r0 + 8) * ROWF + kk + q],     ah[mf][1], al[mf][1]);
                split_tf32(As[r0 * ROWF + kk + q + 4],       ah[mf][2], al[mf][2]);
                split_tf32(As[(r0 + 8) * ROWF + kk + q + 4], ah[mf][3], al[mf][3]);
            }
#pragma unroll
            for (int nf = 0; nf < 4; nf++) {
                int n0 = wn * 32 + nf * 8 + g;
                split_tf32(Bs[n0 * ROWF + kk + q],     bh[nf][0], bl[nf][0]);
                split_tf32(Bs[n0 * ROWF + kk + q + 4], bh[nf][1], bl[nf][1]);
            }
#pragma unroll
            for (int mf = 0; mf < 4; mf++)
#pragma unroll
                for (int nf = 0; nf < 4; nf++) {
                    mma_tf32(c[mf][nf], ah[mf], bh[nf]);
                    mma_tf32(c[mf][nf], al[mf], bh[nf]);
                    mma_tf32(c[mf][nf], ah[mf], bl[nf]);
                }
        }

        __syncthreads();
        if (kt + 2 < 16) load_stage((kt + 2) % STAGES, kt + 2);
        CP_COMMIT();
    }

    // -------- epilogue (registers only) --------
#pragma unroll
    for (int mf = 0; mf < 4; mf++) {
#pragma unroll
        for (int rr = 0; rr < 2; rr++) {
            int m  = bm + wm * 64 + mf * 16 + g + rr * 8;
#pragma unroll
            for (int nf = 0; nf < 4; nf++) {
                int n = bn + wn * 32 + nf * 8 + 2 * q;
                float v0 = c[mf][nf][rr * 2 + 0];
                float v1 = c[mf][nf][rr * 2 + 1];
                if (MODE == 0) {
                    int bI = m >> 8, t = m & 255;
                    int sec = n >> 9, h = (n >> 6) & 7, d = n & 63;
                    float* dst = (sec == 0) ? g_q : ((sec == 1) ? g_k : g_v);
                    if (sec < 2) {
                        float co = __ldg(cosT + t * HD + d);
                        float sn = __ldg(sinT + t * HD + d);
                        float t0 = v0 * co - v1 * sn;
                        float t1 = v1 * co + v0 * sn;
                        v0 = t0; v1 = t1;
                    }
                    *(float2*)(dst + ((((size_t)bI * HH + h) * TT + t) * HD + d)) =
                        make_float2(v0, v1);
                } else {
                    *(float2*)(dst_out + (size_t)m * DD + n) = make_float2(v0, v1);
                }
            }
        }
    }
}

// ---------------------------------------------------------------------------
// Kernel 2: causal flash attention (fp32 SIMT, unchanged — known good)
// ---------------------------------------------------------------------------
__global__ void __launch_bounds__(256) attn_kernel()
{
    const int qt = blockIdx.x;
    const int bh = blockIdx.y;
    const float* Qg = g_q + ((size_t)bh * TT + qt * 64) * HD;
    const float* Kg = g_k + (size_t)bh * TT * HD;
    const float* Vg = g_v + (size_t)bh * TT * HD;

    __shared__ float Qs[64][64];
    __shared__ float KP[64][64];
    __shared__ float Vs[64][64];

    const int tid = threadIdx.x;
    const int ty = tid >> 4;
    const int tx = tid & 15;

#pragma unroll
    for (int l = 0; l < 4; l++) {
        int f = tid + l * 256;
        int r = f >> 4, c4 = f & 15;
        *(float4*)&Qs[r][c4 * 4] = *(const float4*)(Qg + r * HD + c4 * 4);
    }

    float O[4][4];
    float mrow[4], lrow[4];
#pragma unroll
    for (int i = 0; i < 4; i++) {
        mrow[i] = -3.0e38f;
        lrow[i] = 0.f;
#pragma unroll
        for (int j = 0; j < 4; j++) O[i][j] = 0.f;
    }

    const float scale = 0.125f;

    for (int kt = 0; kt <= qt; kt++) {
        __syncthreads();
#pragma unroll
        for (int l = 0; l < 4; l++) {
            int f = tid + l * 256;
            int r = f >> 4, c4 = f & 15;
            const float* kp = Kg + ((size_t)kt * 64 + r) * HD + c4 * 4;
            float4 kv = *(const float4*)kp;
            int d0 = c4 * 4;
            KP[r][(d0 + 0 + r) & 63] = kv.x;
            KP[r][(d0 + 1 + r) & 63] = kv.y;
            KP[r][(d0 + 2 + r) & 63] = kv.z;
            KP[r][(d0 + 3 + r) & 63] = kv.w;
            *(float4*)&Vs[r][c4 * 4] =
                *(const float4*)(Vg + ((size_t)kt * 64 + r) * HD + c4 * 4);
        }
        __syncthreads();

        float S[4][4];
#pragma unroll
        for (int i = 0; i < 4; i++)
#pragma unroll
            for (int j = 0; j < 4; j++) S[i][j] = 0.f;

#pragma unroll 8
        for (int d = 0; d < 64; d++) {
            float a[4], b[4];
#pragma unroll
            for (int i = 0; i < 4; i++) a[i] = Qs[ty * 4 + i][d];
#pragma unroll
            for (int j = 0; j < 4; j++) {
                int cc = tx * 4 + j;
                b[j] = KP[cc][(d + cc) & 63];
            }
#pragma unroll
            for (int i = 0; i < 4; i++)
#pragma unroll
                for (int j = 0; j < 4; j++) S[i][j] += a[i] * b[j];
        }

        if (kt == qt) {
#pragma unroll
            for (int i = 0; i < 4; i++)
#pragma unroll
                for (int j = 0; j < 4; j++) {
                    int qr = ty * 4 + i, kc = tx * 4 + j;
                    S[i][j] = (kc > qr) ? -3.0e38f : S[i][j] * scale;
                }
        } else {
#pragma unroll
            for (int i = 0; i < 4; i++)
#pragma unroll
                for (int j = 0; j < 4; j++) S[i][j] *= scale;
        }

#pragma unroll
        for (int i = 0; i < 4; i++) {
            float mloc = S[i][0];
#pragma unroll
            for (int j = 1; j < 4; j++) mloc = fmaxf(mloc, S[i][j]);
#pragma unroll
            for (int off = 8; off >= 1; off >>= 1)
                mloc = fmaxf(mloc, __shfl_xor_sync(0xffffffffu, mloc, off, 16));
            float mnew = fmaxf(mrow[i], mloc);
            float alpha = expf(mrow[i] - mnew);
            float psum = 0.f;
#pragma unroll
            for (int j = 0; j < 4; j++) {
                float p = expf(S[i][j] - mnew);
                S[i][j] = p;
                psum += p;
            }
#pragma unroll
            for (int off = 8; off >= 1; off >>= 1)
                psum += __shfl_xor_sync(0xffffffffu, psum, off, 16);
            lrow[i] = lrow[i] * alpha + psum;
            mrow[i] = mnew;
#pragma unroll
            for (int j = 0; j < 4; j++) O[i][j] *= alpha;
        }

        __syncthreads();
#pragma unroll
        for (int i = 0; i < 4; i++) {
            float4 p4 = make_float4(S[i][0], S[i][1], S[i][2], S[i][3]);
            *(float4*)&KP[ty * 4 + i][tx * 4] = p4;
        }
        __syncthreads();

#pragma unroll 8
        for (int cc = 0; cc < 64; cc++) {
            float p[4], vv[4];
#pragma unroll
            for (int i = 0; i < 4; i++) p[i] = KP[ty * 4 + i][cc];
#pragma unroll
            for (int j = 0; j < 4; j++) vv[j] = Vs[cc][tx * 4 + j];
#pragma unroll
            for (int i = 0; i < 4; i++)
#pragma unroll
                for (int j = 0; j < 4; j++) O[i][j] += p[i] * vv[j];
        }
    }

    const int b = bh >> 3;
    const int h = bh & 7;
#pragma unroll
    for (int i = 0; i < 4; i++) {
        float inv = 1.f / lrow[i];
        int t = qt * 64 + ty * 4 + i;
        float4 o = make_float4(O[i][0] * inv, O[i][1] * inv,
                               O[i][2] * inv, O[i][3] * inv);
        *(float4*)(g_att + ((size_t)b * TT + t) * DD + h * HD + tx * 4) = o;
    }
}

// ---------------------------------------------------------------------------
extern "C" void kernel_launch(void* const* d_in, const int* in_sizes, int n_in,
                              void* d_out, int out_size)
{
    const float* x    = (const float*)d_in[0];
    const float* cosT = (const float*)d_in[1];
    const float* sinT = (const float*)d_in[2];
    const float* Wqkv = (const float*)d_in[3];
    const float* Wout = (const float*)d_in[4];
    float* out = (float*)d_out;

    cudaFuncSetAttribute(mma_gemm_kernel<0>,
                         cudaFuncAttributeMaxDynamicSharedMemorySize, SMEM_BYTES);
    cudaFuncSetAttribute(mma_gemm_kernel<1>,
                         cudaFuncAttributeMaxDynamicSharedMemorySize, SMEM_BYTES);

    dim3 g1(12, 512);   // N=1536, M=65536
    mma_gemm_kernel<0><<<g1, 256, SMEM_BYTES>>>(x, Wqkv, cosT, sinT, nullptr);

    dim3 ga(4, BB * HH);
    attn_kernel<<<ga, 256>>>();

    dim3 g2(4, 512);    // N=512
    mma_gemm_kernel<1><<<g2, 256, SMEM_BYTES>>>(nullptr, Wout, cosT, sinT, out);
}

// round 6
// speedup vs baseline: 1.7160x; 1.3513x over previous
#include <cuda_runtime.h>
#include <cstdint>

// Problem constants
#define BB 256
#define TT 256
#define DD 512
#define HH 8
#define HD 64
#define KDIM 512

// Scratch (device globals; no allocation allowed)
__device__ float g_q[BB * HH * TT * HD];   // [B,H,T,HD]
__device__ float g_k[BB * HH * TT * HD];
__device__ float g_v[BB * HH * TT * HD];
__device__ float g_att[BB * TT * DD];      // [B,T,D]

// ---------------------------------------------------------------------------
// helpers
// ---------------------------------------------------------------------------
__device__ __forceinline__ void mma_bf16(float* c, const uint32_t* a, const uint32_t* b) {
    asm volatile(
        "mma.sync.aligned.m16n8k16.row.col.f32.bf16.bf16.f32 "
        "{%0,%1,%2,%3}, {%4,%5,%6,%7}, {%8,%9}, {%0,%1,%2,%3};"
        : "+f"(c[0]), "+f"(c[1]), "+f"(c[2]), "+f"(c[3])
        : "r"(a[0]), "r"(a[1]), "r"(a[2]), "r"(a[3]), "r"(b[0]), "r"(b[1]));
}

// split two fp32 (consecutive k) into packed bf16x2 hi and lo pairs
__device__ __forceinline__ void split_pair(float x0, float x1,
                                           uint32_t& hi, uint32_t& lo) {
    asm("cvt.rn.bf16x2.f32 %0, %1, %2;" : "=r"(hi) : "f"(x1), "f"(x0));
    float h0 = __uint_as_float(hi << 16);
    float h1 = __uint_as_float(hi & 0xffff0000u);
    asm("cvt.rn.bf16x2.f32 %0, %1, %2;" : "=r"(lo) : "f"(x1 - h1), "f"(x0 - h0));
}

// ---------------------------------------------------------------------------
// 3xBF16 tensor-core GEMM: C[128x128] = A[128xK] @ W[128xK]^T (both K-major)
// MODE 0: A = x; epilogue applies RoPE, scatters to g_q/g_k/g_v
// MODE 1: A = g_att; epilogue writes dst_out
// 512 threads = 16 warps (4m x 4n); warp tile 32x32; BK=32; 2-stage smem.
// smem entry: uint2 {bf16x2 hi pair, bf16x2 lo pair} per k-pair.
// Row stride 20 uint2 (16 pairs + 4 pad) -> conflict-free 64-bit LDS.
// Precision: C += Ah*Bh + Al*Bh + Ah*Bl  (lo*lo ~2^-18, negligible).
// ---------------------------------------------------------------------------
#define RP2 20
#define TILE_U2 (128 * RP2)            // 2560 uint2 per matrix per stage
#define STG_U2  (2 * TILE_U2)          // A + B
#define SMEM_BYTES (2 * STG_U2 * 8)    // 81920

template <int MODE>
__global__ void __launch_bounds__(512) mma_gemm_kernel(
    const float* __restrict__ Ain,
    const float* __restrict__ W,
    const float* __restrict__ cosT,
    const float* __restrict__ sinT,
    float* __restrict__ dst_out)
{
    extern __shared__ uint2 sm2[];
    const float* A = (MODE == 0) ? Ain : (const float*)g_att;

    const int tid  = threadIdx.x;
    const int wid  = tid >> 5;
    const int lane = tid & 31;
    const int g    = lane >> 2;     // group 0..7
    const int q    = lane & 3;      // quad  0..3
    const int bm   = blockIdx.y * 128;
    const int bn   = blockIdx.x * 128;
    const int wm   = wid & 3;       // warp m index (4)
    const int wn   = wid >> 2;      // warp n index (4)

    float c[2][4][4];
#pragma unroll
    for (int mf = 0; mf < 2; mf++)
#pragma unroll
        for (int nf = 0; nf < 4; nf++)
#pragma unroll
            for (int r = 0; r < 4; r++) c[mf][nf][r] = 0.f;

    // register staging: 2 float4 of A + 2 of B per thread per stage
    float4 ra[2], rb[2];

    auto load_regs = [&](int kt) {
        const float* ag = A + (size_t)bm * KDIM + kt * 32;
        const float* bg = W + (size_t)bn * KDIM + kt * 32;
#pragma unroll
        for (int i = 0; i < 2; i++) {
            int e   = tid + i * 512;
            int row = e >> 3;
            int k4  = e & 7;
            ra[i] = *(const float4*)(ag + (size_t)row * KDIM + k4 * 4);
            rb[i] = *(const float4*)(bg + (size_t)row * KDIM + k4 * 4);
        }
    };

    auto store_stage = [&](int s) {
        uint2* as = sm2 + s * STG_U2;
        uint2* bs = as + TILE_U2;
#pragma unroll
        for (int i = 0; i < 2; i++) {
            int e   = tid + i * 512;
            int row = e >> 3;
            int k4  = e & 7;
            uint2 p0, p1;
            split_pair(ra[i].x, ra[i].y, p0.x, p0.y);
            split_pair(ra[i].z, ra[i].w, p1.x, p1.y);
            as[row * RP2 + 2 * k4]     = p0;
            as[row * RP2 + 2 * k4 + 1] = p1;
            split_pair(rb[i].x, rb[i].y, p0.x, p0.y);
            split_pair(rb[i].z, rb[i].w, p1.x, p1.y);
            bs[row * RP2 + 2 * k4]     = p0;
            bs[row * RP2 + 2 * k4 + 1] = p1;
        }
    };

    load_regs(0);

#pragma unroll 1
    for (int kt = 0; kt < 16; kt++) {
        store_stage(kt & 1);
        if (kt + 1 < 16) load_regs(kt + 1);   // in flight during compute
        __syncthreads();

        const uint2* as = sm2 + (kt & 1) * STG_U2;
        const uint2* bs = as + TILE_U2;
#pragma unroll
        for (int s2 = 0; s2 < 2; s2++) {
            const int c0 = s2 * 8;
            uint32_t ah[2][4], al[2][4], bh[4][2], bl[4][2];
#pragma unroll
            for (int mf = 0; mf < 2; mf++) {
                int r0 = wm * 32 + mf * 16 + g;
                uint2 p0 = as[r0 * RP2 + c0 + q];
                uint2 p1 = as[(r0 + 8) * RP2 + c0 + q];
                uint2 p2 = as[r0 * RP2 + c0 + q + 4];
                uint2 p3 = as[(r0 + 8) * RP2 + c0 + q + 4];
                ah[mf][0] = p0.x; ah[mf][1] = p1.x; ah[mf][2] = p2.x; ah[mf][3] = p3.x;
                al[mf][0] = p0.y; al[mf][1] = p1.y; al[mf][2] = p2.y; al[mf][3] = p3.y;
            }
#pragma unroll
            for (int nf = 0; nf < 4; nf++) {
                int n0 = wn * 32 + nf * 8 + g;
                uint2 q0 = bs[n0 * RP2 + c0 + q];
                uint2 q1 = bs[n0 * RP2 + c0 + q + 4];
                bh[nf][0] = q0.x; bh[nf][1] = q1.x;
                bl[nf][0] = q0.y; bl[nf][1] = q1.y;
            }
#pragma unroll
            for (int mf = 0; mf < 2; mf++)
#pragma unroll
                for (int nf = 0; nf < 4; nf++) {
                    mma_bf16(c[mf][nf], ah[mf], bh[nf]);
                    mma_bf16(c[mf][nf], al[mf], bh[nf]);
                    mma_bf16(c[mf][nf], ah[mf], bl[nf]);
                }
        }
        // next iter stores to the other buffer, whose readers (compute kt-1)
        // all finished before this iteration's __syncthreads -> no extra sync
    }

    // -------- epilogue (registers only) --------
#pragma unroll
    for (int mf = 0; mf < 2; mf++) {
#pragma unroll
        for (int rr = 0; rr < 2; rr++) {
            int m = bm + wm * 32 + mf * 16 + g + rr * 8;
#pragma unroll
            for (int nf = 0; nf < 4; nf++) {
                int n = bn + wn * 32 + nf * 8 + 2 * q;
                float v0 = c[mf][nf][rr * 2 + 0];
                float v1 = c[mf][nf][rr * 2 + 1];
                if (MODE == 0) {
                    int bI = m >> 8, t = m & 255;
                    int sec = n >> 9, h = (n >> 6) & 7, d = n & 63;
                    float* dst = (sec == 0) ? g_q : ((sec == 1) ? g_k : g_v);
                    if (sec < 2) {
                        float co = __ldg(cosT + t * HD + d);
                        float sn = __ldg(sinT + t * HD + d);
                        float t0 = v0 * co - v1 * sn;
                        float t1 = v1 * co + v0 * sn;
                        v0 = t0; v1 = t1;
                    }
                    *(float2*)(dst + ((((size_t)bI * HH + h) * TT + t) * HD + d)) =
                        make_float2(v0, v1);
                } else {
                    *(float2*)(dst_out + (size_t)m * DD + n) = make_float2(v0, v1);
                }
            }
        }
    }
}

// ---------------------------------------------------------------------------
// Kernel 2: causal flash attention (fp32 SIMT, unchanged — known good)
// ---------------------------------------------------------------------------
__global__ void __launch_bounds__(256) attn_kernel()
{
    const int qt = blockIdx.x;
    const int bh = blockIdx.y;
    const float* Qg = g_q + ((size_t)bh * TT + qt * 64) * HD;
    const float* Kg = g_k + (size_t)bh * TT * HD;
    const float* Vg = g_v + (size_t)bh * TT * HD;

    __shared__ float Qs[64][64];
    __shared__ float KP[64][64];
    __shared__ float Vs[64][64];

    const int tid = threadIdx.x;
    const int ty = tid >> 4;
    const int tx = tid & 15;

#pragma unroll
    for (int l = 0; l < 4; l++) {
        int f = tid + l * 256;
        int r = f >> 4, c4 = f & 15;
        *(float4*)&Qs[r][c4 * 4] = *(const float4*)(Qg + r * HD + c4 * 4);
    }

    float O[4][4];
    float mrow[4], lrow[4];
#pragma unroll
    for (int i = 0; i < 4; i++) {
        mrow[i] = -3.0e38f;
        lrow[i] = 0.f;
#pragma unroll
        for (int j = 0; j < 4; j++) O[i][j] = 0.f;
    }

    const float scale = 0.125f;

    for (int kt = 0; kt <= qt; kt++) {
        __syncthreads();
#pragma unroll
        for (int l = 0; l < 4; l++) {
            int f = tid + l * 256;
            int r = f >> 4, c4 = f & 15;
            const float* kp = Kg + ((size_t)kt * 64 + r) * HD + c4 * 4;
            float4 kv = *(const float4*)kp;
            int d0 = c4 * 4;
            KP[r][(d0 + 0 + r) & 63] = kv.x;
            KP[r][(d0 + 1 + r) & 63] = kv.y;
            KP[r][(d0 + 2 + r) & 63] = kv.z;
            KP[r][(d0 + 3 + r) & 63] = kv.w;
            *(float4*)&Vs[r][c4 * 4] =
                *(const float4*)(Vg + ((size_t)kt * 64 + r) * HD + c4 * 4);
        }
        __syncthreads();

        float S[4][4];
#pragma unroll
        for (int i = 0; i < 4; i++)
#pragma unroll
            for (int j = 0; j < 4; j++) S[i][j] = 0.f;

#pragma unroll 8
        for (int d = 0; d < 64; d++) {
            float a[4], b[4];
#pragma unroll
            for (int i = 0; i < 4; i++) a[i] = Qs[ty * 4 + i][d];
#pragma unroll
            for (int j = 0; j < 4; j++) {
                int cc = tx * 4 + j;
                b[j] = KP[cc][(d + cc) & 63];
            }
#pragma unroll
            for (int i = 0; i < 4; i++)
#pragma unroll
                for (int j = 0; j < 4; j++) S[i][j] += a[i] * b[j];
        }

        if (kt == qt) {
#pragma unroll
            for (int i = 0; i < 4; i++)
#pragma unroll
                for (int j = 0; j < 4; j++) {
                    int qr = ty * 4 + i, kc = tx * 4 + j;
                    S[i][j] = (kc > qr) ? -3.0e38f : S[i][j] * scale;
                }
        } else {
#pragma unroll
            for (int i = 0; i < 4; i++)
#pragma unroll
                for (int j = 0; j < 4; j++) S[i][j] *= scale;
        }

#pragma unroll
        for (int i = 0; i < 4; i++) {
            float mloc = S[i][0];
#pragma unroll
            for (int j = 1; j < 4; j++) mloc = fmaxf(mloc, S[i][j]);
#pragma unroll
            for (int off = 8; off >= 1; off >>= 1)
                mloc = fmaxf(mloc, __shfl_xor_sync(0xffffffffu, mloc, off, 16));
            float mnew = fmaxf(mrow[i], mloc);
            float alpha = expf(mrow[i] - mnew);
            float psum = 0.f;
#pragma unroll
            for (int j = 0; j < 4; j++) {
                float p = expf(S[i][j] - mnew);
                S[i][j] = p;
                psum += p;
            }
#pragma unroll
            for (int off = 8; off >= 1; off >>= 1)
                psum += __shfl_xor_sync(0xffffffffu, psum, off, 16);
            lrow[i] = lrow[i] * alpha + psum;
            mrow[i] = mnew;
#pragma unroll
            for (int j = 0; j < 4; j++) O[i][j] *= alpha;
        }

        __syncthreads();
#pragma unroll
        for (int i = 0; i < 4; i++) {
            float4 p4 = make_float4(S[i][0], S[i][1], S[i][2], S[i][3]);
            *(float4*)&KP[ty * 4 + i][tx * 4] = p4;
        }
        __syncthreads();

#pragma unroll 8
        for (int cc = 0; cc < 64; cc++) {
            float p[4], vv[4];
#pragma unroll
            for (int i = 0; i < 4; i++) p[i] = KP[ty * 4 + i][cc];
#pragma unroll
            for (int j = 0; j < 4; j++) vv[j] = Vs[cc][tx * 4 + j];
#pragma unroll
            for (int i = 0; i < 4; i++)
#pragma unroll
                for (int j = 0; j < 4; j++) O[i][j] += p[i] * vv[j];
        }
    }

    const int b = bh >> 3;
    const int h = bh & 7;
#pragma unroll
    for (int i = 0; i < 4; i++) {
        float inv = 1.f / lrow[i];
        int t = qt * 64 + ty * 4 + i;
        float4 o = make_float4(O[i][0] * inv, O[i][1] * inv,
                               O[i][2] * inv, O[i][3] * inv);
        *(float4*)(g_att + ((size_t)b * TT + t) * DD + h * HD + tx * 4) = o;
    }
}

// ---------------------------------------------------------------------------
extern "C" void kernel_launch(void* const* d_in, const int* in_sizes, int n_in,
                              void* d_out, int out_size)
{
    const float* x    = (const float*)d_in[0];
    const float* cosT = (const float*)d_in[1];
    const float* sinT = (const float*)d_in[2];
    const float* Wqkv = (const float*)d_in[3];
    const float* Wout = (const float*)d_in[4];
    float* out = (float*)d_out;

    cudaFuncSetAttribute(mma_gemm_kernel<0>,
                         cudaFuncAttributeMaxDynamicSharedMemorySize, SMEM_BYTES);
    cudaFuncSetAttribute(mma_gemm_kernel<1>,
                         cudaFuncAttributeMaxDynamicSharedMemorySize, SMEM_BYTES);

    dim3 g1(12, 512);   // N=1536, M=65536
    mma_gemm_kernel<0><<<g1, 512, SMEM_BYTES>>>(x, Wqkv, cosT, sinT, nullptr);

    dim3 ga(4, BB * HH);
    attn_kernel<<<ga, 256>>>();

    dim3 g2(4, 512);    // N=512
    mma_gemm_kernel<1><<<g2, 512, SMEM_BYTES>>>(nullptr, Wout, cosT, sinT, out);
}